// round 9
// baseline (speedup 1.0000x reference)
#include <cuda_runtime.h>
#include <cstdint>
#include <math.h>

#define NIR 10
#define EPS2 1e-12f
#define INV_SQRT10 0.31622776601683794f

#define TABN 256
#define RMAX 8.0f
#define DELTA (RMAX / (float)TABN)
#define INV_DELTA ((float)TABN / RMAX)

// coefficient table: h_v(r) ~= a_v + b_v*r on interval k.
// row layout: 7 x float4; j in 0..4 holds (a_{2j}, b_{2j}, a_{2j+1}, b_{2j+1}); j=5,6 pad.
__device__ __align__(16) float4 g_tab[TABN][7];

// weights in constant memory: [0..99] W2T pair-quads, [100..109] W1x,
// [110..119] W1y, [120..129] b1, [130..139] b2
__constant__ __align__(16) float cParams[144];
__device__  __align__(16) float g_stage[144];

static __device__ __forceinline__ float ex2f(float x){ float r; asm("ex2.approx.f32 %0, %1;" : "=f"(r) : "f"(x)); return r; }
static __device__ __forceinline__ float rcpf(float x){ float r; asm("rcp.approx.f32 %0, %1;" : "=f"(r) : "f"(x)); return r; }
static __device__ __forceinline__ float rsqf(float x){ float r; asm("rsqrt.approx.f32 %0, %1;" : "=f"(r) : "f"(x)); return r; }
static __device__ __forceinline__ float sqrtaf(float x){ float r; asm("sqrt.approx.f32 %0, %1;" : "=f"(r) : "f"(x)); return r; }

static __device__ __forceinline__ float tanh_fast(float z){
    float e = ex2f(z * 2.8853900817779268f);
    float r = rcpf(e + 1.0f);
    return fmaf(-2.0f, r, 1.0f);
}

static __device__ __forceinline__ uint64_t pack2(float lo, float hi){
    uint64_t r; asm("mov.b64 %0, {%1, %2};" : "=l"(r) : "f"(lo), "f"(hi)); return r;
}
static __device__ __forceinline__ float2 unpack2(uint64_t v){
    float2 f; asm("mov.b64 {%0, %1}, %2;" : "=f"(f.x), "=f"(f.y) : "l"(v)); return f;
}
static __device__ __forceinline__ uint64_t fma2(uint64_t a, uint64_t b, uint64_t c){
    uint64_t d; asm("fma.rn.f32x2 %0, %1, %2, %3;" : "=l"(d) : "l"(a), "l"(b), "l"(c)); return d;
}
static __device__ __forceinline__ uint64_t add2(uint64_t a, uint64_t b){
    uint64_t d; asm("add.rn.f32x2 %0, %1, %2;" : "=l"(d) : "l"(a), "l"(b)); return d;
}
static __device__ __forceinline__ uint64_t lo64(float4 w){ return pack2(w.x, w.y); }
static __device__ __forceinline__ uint64_t hi64(float4 w){ return pack2(w.z, w.w); }

// ---------------- table build + weight staging ----------------
static __device__ void eval_h(float r,
                              const float* __restrict__ lw1, const float* __restrict__ nb1,
                              const float* __restrict__ lw2, const float* __restrict__ nb2,
                              const float* __restrict__ wf, float* h)
{
    float n2 = r * r;
    float g[NIR];
    #pragma unroll
    for (int u = 0; u < NIR; u++){
        float a   = lw1[u];
        float arg = fmaf(a * a, n2, EPS2);
        float inv = rsqf(arg);
        float nrm = arg * inv;
        g[u] = tanh_fast(nrm + nb1[u]) * inv;
    }
    #pragma unroll
    for (int v = 0; v < NIR; v++){
        float c = 0.0f;
        #pragma unroll
        for (int u = 0; u < NIR; u++)
            c = fmaf(g[u] * lw1[u], lw2[u * NIR + v], c);
        c *= INV_SQRT10;
        float arg = fmaf(c * c, n2, EPS2);
        float inv = rsqf(arg);
        float nrm = arg * inv;
        float scal2 = tanh_fast(nrm + nb2[v]) * inv;
        h[v] = c * scal2 * wf[v] * INV_SQRT10;
    }
}

__global__ void build_table(const float* __restrict__ lw1, const float* __restrict__ nb1,
                            const float* __restrict__ lw2, const float* __restrict__ nb2,
                            const float* __restrict__ wf,
                            const float* __restrict__ W1, const float* __restrict__ b1,
                            const float* __restrict__ W2, const float* __restrict__ b2)
{
    int k = threadIdx.x;   // 0..255

    // stage permuted weights
    if (k < 100){
        int u = k / 10, v = k % 10;
        g_stage[(v >> 1) * 20 + (u >> 1) * 4 + ((u & 1) << 1) + (v & 1)] = W2[k];
    } else if (k < 110) g_stage[k] = W1[k - 100];
    else if (k < 120)   g_stage[k] = W1[k - 110 + 10];
    else if (k < 130)   g_stage[k] = b1[k - 120];
    else if (k < 140)   g_stage[k] = b2[k - 130];
    else if (k < 144)   g_stage[k] = 0.0f;

    if (k >= TABN) return;
    float r0 = (float)k * DELTA;
    float h0[NIR], h1[NIR];
    eval_h(r0,         lw1, nb1, lw2, nb2, wf, h0);
    eval_h(r0 + DELTA, lw1, nb1, lw2, nb2, wf, h1);
    #pragma unroll
    for (int j = 0; j < 5; j++){
        float bb0 = (h1[2*j]   - h0[2*j])   * INV_DELTA;
        float bb1 = (h1[2*j+1] - h0[2*j+1]) * INV_DELTA;
        float aa0 = fmaf(-bb0, r0, h0[2*j]);
        float aa1 = fmaf(-bb1, r0, h0[2*j+1]);
        g_tab[k][j] = make_float4(aa0, bb0, aa1, bb1);
    }
    g_tab[k][5] = make_float4(0.f, 0.f, 0.f, 0.f);
    g_tab[k][6] = make_float4(0.f, 0.f, 0.f, 0.f);
}

// ---------------- main kernel: warp-per-batch, 3 blocks/SM, register diet ----------------
__global__ __launch_bounds__(256, 3) void trq_2b_kernel(
    const float* __restrict__ v1b,   // (B,3)
    const float* __restrict__ invar, // (B,P,2)
    const float* __restrict__ vec2,  // (B,P,6)
    float* __restrict__ out)         // (B,3)
{
    __shared__ __align__(16) float4 sTab[TABN][7];   // 28672 B

    const int tid = threadIdx.x;

    {
        const float4* src = &g_tab[0][0];
        float4* dst = &sTab[0][0];
        #pragma unroll
        for (int i = tid; i < TABN * 7; i += 256)
            dst[i] = src[i];
    }
    __syncthreads();

    const int w    = tid >> 5;
    const int lane = tid & 31;
    const int b    = blockIdx.x * 8 + w;
    const float4* cW2q = reinterpret_cast<const float4*>(cParams);

    // hoist only the b2 pairs (10 regs); W1/b1 stay on the constant/uniform path
    uint64_t b2d[5];
    #pragma unroll
    for (int j = 0; j < 5; j++) b2d[j] = pack2(cParams[130 + 2*j], cParams[131 + 2*j]);

    const size_t e0 = (size_t)b * 256 + lane;
    const float2* ivp = reinterpret_cast<const float2*>(invar) + e0;
    const float*  vb  = vec2 + e0 * 6;

    // rolling 2-slot prefetch
    float2 iv[2];
    float  vx[2];
    float2 vyz[2];
    #pragma unroll
    for (int s = 0; s < 2; s++){
        iv[s]  = ivp[s * 32];
        const float* vp = vb + s * 192;
        vx[s]  = vp[3];
        vyz[s] = *reinterpret_cast<const float2*>(vp + 4);
    }

    float tx = 0.f, ty = 0.f, tz = 0.f;

    #pragma unroll
    for (int i = 0; i < 8; i++){
        const int cb = i & 1;
        const float2 civ  = iv[cb];
        const float  cvx  = vx[cb];
        const float2 cvyz = vyz[cb];

        // prefetch element i+2 into the slot just consumed
        if (i < 6){
            iv[cb]  = ivp[(i + 2) * 32];
            const float* vp = vb + (i + 2) * 192;
            vx[cb]  = vp[3];
            vyz[cb] = *reinterpret_cast<const float2*>(vp + 4);
        }

        // y1 = relu(invar @ W1 + b1); W1/b1 via constant (uniform) path
        uint64_t y1d[NIR];
        #pragma unroll
        for (int u = 0; u < NIR; u++){
            float y = fmaxf(fmaf(civ.x, cParams[100 + u],
                           fmaf(civ.y, cParams[110 + u], cParams[120 + u])), 0.0f);
            y1d[u] = pack2(y, y);
        }

        // y2 = relu(y1 @ W2 + b2): dual accumulator chains per j
        uint64_t y2d[NIR];
        #pragma unroll
        for (int j = 0; j < 5; j++){
            uint64_t accA = b2d[j];
            uint64_t accB = 0ull;
            #pragma unroll
            for (int uu = 0; uu < 5; uu++){
                float4 wq = cW2q[j * 5 + uu];
                if (uu < 2){
                    accA = fma2(y1d[2*uu],   lo64(wq), accA);
                    accA = fma2(y1d[2*uu+1], hi64(wq), accA);
                } else {
                    accB = fma2(y1d[2*uu],   lo64(wq), accB);
                    accB = fma2(y1d[2*uu+1], hi64(wq), accB);
                }
            }
            float2 rr = unpack2(add2(accA, accB));
            float m0 = fmaxf(rr.x, 0.0f);
            float m1 = fmaxf(rr.y, 0.0f);
            y2d[2*j]   = pack2(m0, m0);
            y2d[2*j+1] = pack2(m1, m1);
        }

        // r = |v|, table row k, dot with (a,b) pairs — two parallel acc chains
        const float n2 = fmaf(cvx, cvx, fmaf(cvyz.x, cvyz.x, cvyz.y * cvyz.y));
        const float r  = sqrtaf(n2);
        int k = (int)(r * INV_DELTA);
        k = (k > TABN - 1) ? (TABN - 1) : k;

        const float4* row = sTab[k];
        uint64_t acc0 = 0ull, acc1 = 0ull;
        #pragma unroll
        for (int j = 0; j < 5; j++){
            float4 t = row[j];
            if (j & 1){
                acc1 = fma2(y2d[2*j],   lo64(t), acc1);
                acc1 = fma2(y2d[2*j+1], hi64(t), acc1);
            } else {
                acc0 = fma2(y2d[2*j],   lo64(t), acc0);
                acc0 = fma2(y2d[2*j+1], hi64(t), acc0);
            }
        }
        float2 sab = unpack2(add2(acc0, acc1));
        const float S = fmaf(r, sab.y, sab.x);

        tx = fmaf(cvx,    S, tx);
        ty = fmaf(cvyz.x, S, ty);
        tz = fmaf(cvyz.y, S, tz);
    }

    // warp reduction (warp owns batch b entirely)
    #pragma unroll
    for (int off = 16; off > 0; off >>= 1){
        tx += __shfl_down_sync(0xFFFFFFFFu, tx, off);
        ty += __shfl_down_sync(0xFFFFFFFFu, ty, off);
        tz += __shfl_down_sync(0xFFFFFFFFu, tz, off);
    }
    if (lane == 0){
        const float a0 = v1b[b*3+0], a1 = v1b[b*3+1], a2 = v1b[b*3+2];
        out[b*3+0] = a1 * tz - a2 * ty;
        out[b*3+1] = a2 * tx - a0 * tz;
        out[b*3+2] = a0 * ty - a1 * tx;
    }
}

extern "C" void kernel_launch(void* const* d_in, const int* in_sizes, int n_in,
                              void* d_out, int out_size)
{
    const float* v1b   = (const float*)d_in[0];
    const float* invar = (const float*)d_in[1];
    const float* vec2  = (const float*)d_in[2];
    const float* W1    = (const float*)d_in[3];
    const float* b1    = (const float*)d_in[4];
    const float* W2    = (const float*)d_in[5];
    const float* b2    = (const float*)d_in[6];
    const float* lw1   = (const float*)d_in[7];
    const float* nb1   = (const float*)d_in[8];
    const float* lw2   = (const float*)d_in[9];
    const float* nb2   = (const float*)d_in[10];
    const float* wf    = (const float*)d_in[11];

    const int B = out_size / 3;        // 4096
    const int nGroups = B / 8;         // 512

    build_table<<<1, 256>>>(lw1, nb1, lw2, nb2, wf, W1, b1, W2, b2);

    void* stage_ptr = nullptr;
    cudaGetSymbolAddress(&stage_ptr, g_stage);
    cudaMemcpyToSymbolAsync(cParams, stage_ptr, 144 * sizeof(float), 0,
                            cudaMemcpyDeviceToDevice, 0);

    trq_2b_kernel<<<nGroups, 256>>>(v1b, invar, vec2, (float*)d_out);
}

// round 10
// speedup vs baseline: 1.4556x; 1.4556x over previous
#include <cuda_runtime.h>
#include <cstdint>
#include <math.h>

#define NIR 10
#define EPS2 1e-12f
#define INV_SQRT10 0.31622776601683794f

#define TABN 256
#define RMAX 8.0f
#define DELTA (RMAX / (float)TABN)
#define INV_DELTA ((float)TABN / RMAX)

// coefficient table: h_v(r) ~= a_v + b_v*r on interval k.
// row layout: 7 x float4; j in 0..4 holds (a_{2j}, b_{2j}, a_{2j+1}, b_{2j+1}); j=5,6 pad.
__device__ __align__(16) float4 g_tab[TABN][7];

// weights in constant memory: [0..99] W2T pair-quads, [100..109] W1x,
// [110..119] W1y, [120..129] b1, [130..139] b2
__constant__ __align__(16) float cParams[144];
__device__  __align__(16) float g_stage[144];

static __device__ __forceinline__ float ex2f(float x){ float r; asm("ex2.approx.f32 %0, %1;" : "=f"(r) : "f"(x)); return r; }
static __device__ __forceinline__ float rcpf(float x){ float r; asm("rcp.approx.f32 %0, %1;" : "=f"(r) : "f"(x)); return r; }
static __device__ __forceinline__ float rsqf(float x){ float r; asm("rsqrt.approx.f32 %0, %1;" : "=f"(r) : "f"(x)); return r; }
static __device__ __forceinline__ float sqrtaf(float x){ float r; asm("sqrt.approx.f32 %0, %1;" : "=f"(r) : "f"(x)); return r; }

static __device__ __forceinline__ float tanh_fast(float z){
    float e = ex2f(z * 2.8853900817779268f);
    float r = rcpf(e + 1.0f);
    return fmaf(-2.0f, r, 1.0f);
}

static __device__ __forceinline__ uint64_t pack2(float lo, float hi){
    uint64_t r; asm("mov.b64 %0, {%1, %2};" : "=l"(r) : "f"(lo), "f"(hi)); return r;
}
static __device__ __forceinline__ float2 unpack2(uint64_t v){
    float2 f; asm("mov.b64 {%0, %1}, %2;" : "=f"(f.x), "=f"(f.y) : "l"(v)); return f;
}
static __device__ __forceinline__ uint64_t fma2(uint64_t a, uint64_t b, uint64_t c){
    uint64_t d; asm("fma.rn.f32x2 %0, %1, %2, %3;" : "=l"(d) : "l"(a), "l"(b), "l"(c)); return d;
}
static __device__ __forceinline__ uint64_t add2(uint64_t a, uint64_t b){
    uint64_t d; asm("add.rn.f32x2 %0, %1, %2;" : "=l"(d) : "l"(a), "l"(b)); return d;
}
static __device__ __forceinline__ uint64_t lo64(float4 w){ return pack2(w.x, w.y); }
static __device__ __forceinline__ uint64_t hi64(float4 w){ return pack2(w.z, w.w); }

// ---------------- table build + weight staging ----------------
static __device__ void eval_h(float r,
                              const float* __restrict__ lw1, const float* __restrict__ nb1,
                              const float* __restrict__ lw2, const float* __restrict__ nb2,
                              const float* __restrict__ wf, float* h)
{
    float n2 = r * r;
    float g[NIR];
    #pragma unroll
    for (int u = 0; u < NIR; u++){
        float a   = lw1[u];
        float arg = fmaf(a * a, n2, EPS2);
        float inv = rsqf(arg);
        float nrm = arg * inv;
        g[u] = tanh_fast(nrm + nb1[u]) * inv;
    }
    #pragma unroll
    for (int v = 0; v < NIR; v++){
        float c = 0.0f;
        #pragma unroll
        for (int u = 0; u < NIR; u++)
            c = fmaf(g[u] * lw1[u], lw2[u * NIR + v], c);
        c *= INV_SQRT10;
        float arg = fmaf(c * c, n2, EPS2);
        float inv = rsqf(arg);
        float nrm = arg * inv;
        float scal2 = tanh_fast(nrm + nb2[v]) * inv;
        h[v] = c * scal2 * wf[v] * INV_SQRT10;
    }
}

__global__ void build_table(const float* __restrict__ lw1, const float* __restrict__ nb1,
                            const float* __restrict__ lw2, const float* __restrict__ nb2,
                            const float* __restrict__ wf,
                            const float* __restrict__ W1, const float* __restrict__ b1,
                            const float* __restrict__ W2, const float* __restrict__ b2)
{
    int k = threadIdx.x;   // 0..255

    // stage permuted weights
    if (k < 100){
        int u = k / 10, v = k % 10;
        g_stage[(v >> 1) * 20 + (u >> 1) * 4 + ((u & 1) << 1) + (v & 1)] = W2[k];
    } else if (k < 110) g_stage[k] = W1[k - 100];
    else if (k < 120)   g_stage[k] = W1[k - 110 + 10];
    else if (k < 130)   g_stage[k] = b1[k - 120];
    else if (k < 140)   g_stage[k] = b2[k - 130];
    else if (k < 144)   g_stage[k] = 0.0f;

    if (k >= TABN) return;
    float r0 = (float)k * DELTA;
    float h0[NIR], h1[NIR];
    eval_h(r0,         lw1, nb1, lw2, nb2, wf, h0);
    eval_h(r0 + DELTA, lw1, nb1, lw2, nb2, wf, h1);
    #pragma unroll
    for (int j = 0; j < 5; j++){
        float bb0 = (h1[2*j]   - h0[2*j])   * INV_DELTA;
        float bb1 = (h1[2*j+1] - h0[2*j+1]) * INV_DELTA;
        float aa0 = fmaf(-bb0, r0, h0[2*j]);
        float aa1 = fmaf(-bb1, r0, h0[2*j+1]);
        g_tab[k][j] = make_float4(aa0, bb0, aa1, bb1);
    }
    g_tab[k][5] = make_float4(0.f, 0.f, 0.f, 0.f);
    g_tab[k][6] = make_float4(0.f, 0.f, 0.f, 0.f);
}

// ---------------- main kernel: persistent, warp-per-batch, fused y2+dot ----------------
__global__ __launch_bounds__(256, 2) void trq_2b_kernel(
    const float* __restrict__ v1b,   // (B,3)
    const float* __restrict__ invar, // (B,P,2)
    const float* __restrict__ vec2,  // (B,P,6)
    float* __restrict__ out,         // (B,3)
    int nGroups)
{
    __shared__ __align__(16) float4 sTab[TABN][7];   // 28672 B

    const int tid = threadIdx.x;

    {
        const float4* src = &g_tab[0][0];
        float4* dst = &sTab[0][0];
        #pragma unroll
        for (int i = tid; i < TABN * 7; i += 256)
            dst[i] = src[i];
    }
    __syncthreads();

    const int w    = tid >> 5;
    const int lane = tid & 31;
    const float4* cW2q = reinterpret_cast<const float4*>(cParams);

    // hoist scalar weights (30 regs) and b2 pairs (10 regs)
    float w1x[NIR], w1y[NIR], bb1[NIR];
    #pragma unroll
    for (int u = 0; u < NIR; u++){
        w1x[u] = cParams[100 + u];
        w1y[u] = cParams[110 + u];
        bb1[u] = cParams[120 + u];
    }
    uint64_t b2d[5];
    #pragma unroll
    for (int j = 0; j < 5; j++) b2d[j] = pack2(cParams[130 + 2*j], cParams[131 + 2*j]);

    for (int g = blockIdx.x; g < nGroups; g += gridDim.x){
        const int b = g * 8 + w;

        const size_t e0 = (size_t)b * 256 + lane;
        const float2* ivp = reinterpret_cast<const float2*>(invar) + e0;
        const float*  vb  = vec2 + e0 * 6;

        // ---- front-batch all global loads (single DRAM exposure) ----
        float2 iv[8];
        float  vx[8];
        float2 vyz[8];
        #pragma unroll
        for (int i = 0; i < 8; i++){
            iv[i]  = ivp[i * 32];
            const float* vp = vb + i * 192;           // 32*6
            vx[i]  = vp[3];
            vyz[i] = *reinterpret_cast<const float2*>(vp + 4);
        }

        float tx = 0.f, ty = 0.f, tz = 0.f;

        #pragma unroll
        for (int i = 0; i < 8; i++){
            // ---- gather index first: LDS latency overlaps the MLP chains ----
            const float n2 = fmaf(vx[i], vx[i], fmaf(vyz[i].x, vyz[i].x, vyz[i].y * vyz[i].y));
            const float r  = sqrtaf(n2);
            int k = (int)(r * INV_DELTA);
            k = (k > TABN - 1) ? (TABN - 1) : k;
            const float4* row = sTab[k];

            // y1 = relu(invar @ W1 + b1), duplicated into f32x2 lanes
            uint64_t y1d[NIR];
            #pragma unroll
            for (int u = 0; u < NIR; u++){
                float y = fmaxf(fmaf(iv[i].x, w1x[u], fmaf(iv[i].y, w1y[u], bb1[u])), 0.0f);
                y1d[u] = pack2(y, y);
            }

            // ---- fused y2 + table-dot: 5 independent j-chains feeding 2 dot accums ----
            uint64_t dA = 0ull, dB = 0ull;
            #pragma unroll
            for (int j = 0; j < 5; j++){
                uint64_t accA = b2d[j];
                uint64_t accB = 0ull;
                #pragma unroll
                for (int uu = 0; uu < 5; uu++){
                    float4 wq = cW2q[j * 5 + uu];
                    if (uu < 2){
                        accA = fma2(y1d[2*uu],   lo64(wq), accA);
                        accA = fma2(y1d[2*uu+1], hi64(wq), accA);
                    } else {
                        accB = fma2(y1d[2*uu],   lo64(wq), accB);
                        accB = fma2(y1d[2*uu+1], hi64(wq), accB);
                    }
                }
                float2 rr = unpack2(add2(accA, accB));
                float m0 = fmaxf(rr.x, 0.0f);
                float m1 = fmaxf(rr.y, 0.0f);
                float4 t = row[j];
                dA = fma2(pack2(m0, m0), lo64(t), dA);
                dB = fma2(pack2(m1, m1), hi64(t), dB);
            }
            float2 sab = unpack2(add2(dA, dB));
            const float S = fmaf(r, sab.y, sab.x);

            tx = fmaf(vx[i],    S, tx);
            ty = fmaf(vyz[i].x, S, ty);
            tz = fmaf(vyz[i].y, S, tz);
        }

        // warp reduction (warp owns batch b entirely)
        #pragma unroll
        for (int off = 16; off > 0; off >>= 1){
            tx += __shfl_down_sync(0xFFFFFFFFu, tx, off);
            ty += __shfl_down_sync(0xFFFFFFFFu, ty, off);
            tz += __shfl_down_sync(0xFFFFFFFFu, tz, off);
        }
        if (lane == 0){
            const float a0 = v1b[b*3+0], a1 = v1b[b*3+1], a2 = v1b[b*3+2];
            out[b*3+0] = a1 * tz - a2 * ty;
            out[b*3+1] = a2 * tx - a0 * tz;
            out[b*3+2] = a0 * ty - a1 * tx;
        }
    }
}

extern "C" void kernel_launch(void* const* d_in, const int* in_sizes, int n_in,
                              void* d_out, int out_size)
{
    const float* v1b   = (const float*)d_in[0];
    const float* invar = (const float*)d_in[1];
    const float* vec2  = (const float*)d_in[2];
    const float* W1    = (const float*)d_in[3];
    const float* b1    = (const float*)d_in[4];
    const float* W2    = (const float*)d_in[5];
    const float* b2    = (const float*)d_in[6];
    const float* lw1   = (const float*)d_in[7];
    const float* nb1   = (const float*)d_in[8];
    const float* lw2   = (const float*)d_in[9];
    const float* nb2   = (const float*)d_in[10];
    const float* wf    = (const float*)d_in[11];

    const int B = out_size / 3;        // 4096
    const int nGroups = B / 8;         // 512

    build_table<<<1, 256>>>(lw1, nb1, lw2, nb2, wf, W1, b1, W2, b2);

    void* stage_ptr = nullptr;
    cudaGetSymbolAddress(&stage_ptr, g_stage);
    cudaMemcpyToSymbolAsync(cParams, stage_ptr, 144 * sizeof(float), 0,
                            cudaMemcpyDeviceToDevice, 0);

    int grid = 304;                    // 2 blocks/SM x 152 SMs, wave-perfect
    if (grid > nGroups) grid = nGroups;
    trq_2b_kernel<<<grid, 256>>>(v1b, invar, vec2, (float*)d_out, nGroups);
}

// round 11
// speedup vs baseline: 1.5000x; 1.0305x over previous
#include <cuda_runtime.h>
#include <cstdint>
#include <math.h>

#define NIR 10
#define EPS2 1e-12f
#define INV_SQRT10 0.31622776601683794f

#define TABN 256
#define RMAX 8.0f
#define DELTA (RMAX / (float)TABN)
#define INV_DELTA ((float)TABN / RMAX)

// coefficient table: h_v(r) ~= a_v + b_v*r on interval k.
// row layout: 7 x float4; j in 0..4 holds (a_{2j}, b_{2j}, a_{2j+1}, b_{2j+1}); j=5,6 pad.
__device__ __align__(16) float4 g_tab[TABN][7];

// weights in constant memory: [0..99] W2T pair-quads, [100..109] W1x,
// [110..119] W1y, [120..129] b1, [130..139] b2
__constant__ __align__(16) float cParams[144];
__device__  __align__(16) float g_stage[144];

static __device__ __forceinline__ float ex2f(float x){ float r; asm("ex2.approx.f32 %0, %1;" : "=f"(r) : "f"(x)); return r; }
static __device__ __forceinline__ float rcpf(float x){ float r; asm("rcp.approx.f32 %0, %1;" : "=f"(r) : "f"(x)); return r; }
static __device__ __forceinline__ float rsqf(float x){ float r; asm("rsqrt.approx.f32 %0, %1;" : "=f"(r) : "f"(x)); return r; }
static __device__ __forceinline__ float sqrtaf(float x){ float r; asm("sqrt.approx.f32 %0, %1;" : "=f"(r) : "f"(x)); return r; }

static __device__ __forceinline__ float tanh_fast(float z){
    float e = ex2f(z * 2.8853900817779268f);
    float r = rcpf(e + 1.0f);
    return fmaf(-2.0f, r, 1.0f);
}

static __device__ __forceinline__ uint64_t pack2(float lo, float hi){
    uint64_t r; asm("mov.b64 %0, {%1, %2};" : "=l"(r) : "f"(lo), "f"(hi)); return r;
}
static __device__ __forceinline__ float2 unpack2(uint64_t v){
    float2 f; asm("mov.b64 {%0, %1}, %2;" : "=f"(f.x), "=f"(f.y) : "l"(v)); return f;
}
static __device__ __forceinline__ uint64_t fma2(uint64_t a, uint64_t b, uint64_t c){
    uint64_t d; asm("fma.rn.f32x2 %0, %1, %2, %3;" : "=l"(d) : "l"(a), "l"(b), "l"(c)); return d;
}
static __device__ __forceinline__ uint64_t add2(uint64_t a, uint64_t b){
    uint64_t d; asm("add.rn.f32x2 %0, %1, %2;" : "=l"(d) : "l"(a), "l"(b)); return d;
}
static __device__ __forceinline__ uint64_t lo64(float4 w){ return pack2(w.x, w.y); }
static __device__ __forceinline__ uint64_t hi64(float4 w){ return pack2(w.z, w.w); }

// ---------------- table build + weight staging ----------------
static __device__ void eval_h(float r,
                              const float* __restrict__ lw1, const float* __restrict__ nb1,
                              const float* __restrict__ lw2, const float* __restrict__ nb2,
                              const float* __restrict__ wf, float* h)
{
    float n2 = r * r;
    float g[NIR];
    #pragma unroll
    for (int u = 0; u < NIR; u++){
        float a   = lw1[u];
        float arg = fmaf(a * a, n2, EPS2);
        float inv = rsqf(arg);
        float nrm = arg * inv;
        g[u] = tanh_fast(nrm + nb1[u]) * inv;
    }
    #pragma unroll
    for (int v = 0; v < NIR; v++){
        float c = 0.0f;
        #pragma unroll
        for (int u = 0; u < NIR; u++)
            c = fmaf(g[u] * lw1[u], lw2[u * NIR + v], c);
        c *= INV_SQRT10;
        float arg = fmaf(c * c, n2, EPS2);
        float inv = rsqf(arg);
        float nrm = arg * inv;
        float scal2 = tanh_fast(nrm + nb2[v]) * inv;
        h[v] = c * scal2 * wf[v] * INV_SQRT10;
    }
}

__global__ void build_table(const float* __restrict__ lw1, const float* __restrict__ nb1,
                            const float* __restrict__ lw2, const float* __restrict__ nb2,
                            const float* __restrict__ wf,
                            const float* __restrict__ W1, const float* __restrict__ b1,
                            const float* __restrict__ W2, const float* __restrict__ b2)
{
    int k = threadIdx.x;   // 0..255

    // stage permuted weights
    if (k < 100){
        int u = k / 10, v = k % 10;
        g_stage[(v >> 1) * 20 + (u >> 1) * 4 + ((u & 1) << 1) + (v & 1)] = W2[k];
    } else if (k < 110) g_stage[k] = W1[k - 100];
    else if (k < 120)   g_stage[k] = W1[k - 110 + 10];
    else if (k < 130)   g_stage[k] = b1[k - 120];
    else if (k < 140)   g_stage[k] = b2[k - 130];
    else if (k < 144)   g_stage[k] = 0.0f;

    if (k >= TABN) return;
    float r0 = (float)k * DELTA;
    float h0[NIR], h1[NIR];
    eval_h(r0,         lw1, nb1, lw2, nb2, wf, h0);
    eval_h(r0 + DELTA, lw1, nb1, lw2, nb2, wf, h1);
    #pragma unroll
    for (int j = 0; j < 5; j++){
        float bb0 = (h1[2*j]   - h0[2*j])   * INV_DELTA;
        float bb1 = (h1[2*j+1] - h0[2*j+1]) * INV_DELTA;
        float aa0 = fmaf(-bb0, r0, h0[2*j]);
        float aa1 = fmaf(-bb1, r0, h0[2*j+1]);
        g_tab[k][j] = make_float4(aa0, bb0, aa1, bb1);
    }
    g_tab[k][5] = make_float4(0.f, 0.f, 0.f, 0.f);
    g_tab[k][6] = make_float4(0.f, 0.f, 0.f, 0.f);
}

// ---------------- main kernel: persistent, warp-per-batch, element-PAIR chunks ----------------
__global__ __launch_bounds__(256, 2) void trq_2b_kernel(
    const float* __restrict__ v1b,   // (B,3)
    const float* __restrict__ invar, // (B,P,2)
    const float* __restrict__ vec2,  // (B,P,6)
    float* __restrict__ out,         // (B,3)
    int nGroups)
{
    __shared__ __align__(16) float4 sTab[TABN][7];   // 28672 B

    const int tid = threadIdx.x;

    {
        const float4* src = &g_tab[0][0];
        float4* dst = &sTab[0][0];
        #pragma unroll
        for (int i = tid; i < TABN * 7; i += 256)
            dst[i] = src[i];
    }
    __syncthreads();

    const int w    = tid >> 5;
    const int lane = tid & 31;
    const float4* cW2q = reinterpret_cast<const float4*>(cParams);

    // hoist only b2 pairs (10 regs); W1/b1 go through the uniform LDCU path per use
    uint64_t b2d[5];
    #pragma unroll
    for (int j = 0; j < 5; j++) b2d[j] = pack2(cParams[130 + 2*j], cParams[131 + 2*j]);

    for (int g = blockIdx.x; g < nGroups; g += gridDim.x){
        const int b = g * 8 + w;

        const size_t e0 = (size_t)b * 256 + lane;
        const float2* ivp = reinterpret_cast<const float2*>(invar) + e0;
        const float*  vb  = vec2 + e0 * 6;

        // ---- front-batch all global loads (single DRAM exposure) ----
        float2 iv[8];
        float  vx[8];
        float2 vyz[8];
        #pragma unroll
        for (int i = 0; i < 8; i++){
            iv[i]  = ivp[i * 32];
            const float* vp = vb + i * 192;           // 32*6
            vx[i]  = vp[3];
            vyz[i] = *reinterpret_cast<const float2*>(vp + 4);
        }

        float tx = 0.f, ty = 0.f, tz = 0.f;

        // process elements two at a time: one set of W2 LDCs feeds BOTH chains
        #pragma unroll
        for (int c = 0; c < 4; c++){
            const int iA = 2 * c, iB = 2 * c + 1;

            // gather indices first (LDS latency overlaps MLP)
            const float n2A = fmaf(vx[iA], vx[iA], fmaf(vyz[iA].x, vyz[iA].x, vyz[iA].y * vyz[iA].y));
            const float n2B = fmaf(vx[iB], vx[iB], fmaf(vyz[iB].x, vyz[iB].x, vyz[iB].y * vyz[iB].y));
            const float rA = sqrtaf(n2A);
            const float rB = sqrtaf(n2B);
            int kA = (int)(rA * INV_DELTA); kA = (kA > TABN - 1) ? (TABN - 1) : kA;
            int kB = (int)(rB * INV_DELTA); kB = (kB > TABN - 1) ? (TABN - 1) : kB;
            const float4* rowA = sTab[kA];
            const float4* rowB = sTab[kB];

            // y1 for both elements (W1/b1 via constant/uniform path, shared loads)
            uint64_t y1A[NIR], y1B[NIR];
            #pragma unroll
            for (int u = 0; u < NIR; u++){
                const float w1xu = cParams[100 + u];
                const float w1yu = cParams[110 + u];
                const float b1u  = cParams[120 + u];
                float yA = fmaxf(fmaf(iv[iA].x, w1xu, fmaf(iv[iA].y, w1yu, b1u)), 0.0f);
                float yB = fmaxf(fmaf(iv[iB].x, w1xu, fmaf(iv[iB].y, w1yu, b1u)), 0.0f);
                y1A[u] = pack2(yA, yA);
                y1B[u] = pack2(yB, yB);
            }

            // fused y2 + table-dot, both elements share each W2 quad load
            float SaA = 0.f, SbA = 0.f, SaB = 0.f, SbB = 0.f;
            #pragma unroll
            for (int j = 0; j < 5; j++){
                uint64_t aA = b2d[j], bA = 0ull;
                uint64_t aB = b2d[j], bB = 0ull;
                #pragma unroll
                for (int uu = 0; uu < 5; uu++){
                    float4 wq = cW2q[j * 5 + uu];        // ONE LDC.128 for two elements
                    uint64_t lo = lo64(wq), hi = hi64(wq);
                    aA = fma2(y1A[2*uu],   lo, aA);
                    aB = fma2(y1B[2*uu],   lo, aB);
                    bA = fma2(y1A[2*uu+1], hi, bA);
                    bB = fma2(y1B[2*uu+1], hi, bB);
                }
                float2 yA2 = unpack2(add2(aA, bA));
                float2 yB2 = unpack2(add2(aB, bB));
                const float m0A = fmaxf(yA2.x, 0.f), m1A = fmaxf(yA2.y, 0.f);
                const float m0B = fmaxf(yB2.x, 0.f), m1B = fmaxf(yB2.y, 0.f);
                const float4 tA = rowA[j];
                const float4 tB = rowB[j];
                SaA = fmaf(m0A, tA.x, SaA); SbA = fmaf(m0A, tA.y, SbA);
                SaA = fmaf(m1A, tA.z, SaA); SbA = fmaf(m1A, tA.w, SbA);
                SaB = fmaf(m0B, tB.x, SaB); SbB = fmaf(m0B, tB.y, SbB);
                SaB = fmaf(m1B, tB.z, SaB); SbB = fmaf(m1B, tB.w, SbB);
            }
            const float SA = fmaf(rA, SbA, SaA);
            const float SB = fmaf(rB, SbB, SaB);

            tx = fmaf(vx[iA],    SA, tx);  tx = fmaf(vx[iB],    SB, tx);
            ty = fmaf(vyz[iA].x, SA, ty);  ty = fmaf(vyz[iB].x, SB, ty);
            tz = fmaf(vyz[iA].y, SA, tz);  tz = fmaf(vyz[iB].y, SB, tz);
        }

        // warp reduction (warp owns batch b entirely)
        #pragma unroll
        for (int off = 16; off > 0; off >>= 1){
            tx += __shfl_down_sync(0xFFFFFFFFu, tx, off);
            ty += __shfl_down_sync(0xFFFFFFFFu, ty, off);
            tz += __shfl_down_sync(0xFFFFFFFFu, tz, off);
        }
        if (lane == 0){
            const float a0 = v1b[b*3+0], a1 = v1b[b*3+1], a2 = v1b[b*3+2];
            out[b*3+0] = a1 * tz - a2 * ty;
            out[b*3+1] = a2 * tx - a0 * tz;
            out[b*3+2] = a0 * ty - a1 * tx;
        }
    }
}

extern "C" void kernel_launch(void* const* d_in, const int* in_sizes, int n_in,
                              void* d_out, int out_size)
{
    const float* v1b   = (const float*)d_in[0];
    const float* invar = (const float*)d_in[1];
    const float* vec2  = (const float*)d_in[2];
    const float* W1    = (const float*)d_in[3];
    const float* b1    = (const float*)d_in[4];
    const float* W2    = (const float*)d_in[5];
    const float* b2    = (const float*)d_in[6];
    const float* lw1   = (const float*)d_in[7];
    const float* nb1   = (const float*)d_in[8];
    const float* lw2   = (const float*)d_in[9];
    const float* nb2   = (const float*)d_in[10];
    const float* wf    = (const float*)d_in[11];

    const int B = out_size / 3;        // 4096
    const int nGroups = B / 8;         // 512

    build_table<<<1, 256>>>(lw1, nb1, lw2, nb2, wf, W1, b1, W2, b2);

    void* stage_ptr = nullptr;
    cudaGetSymbolAddress(&stage_ptr, g_stage);
    cudaMemcpyToSymbolAsync(cParams, stage_ptr, 144 * sizeof(float), 0,
                            cudaMemcpyDeviceToDevice, 0);

    int grid = 304;                    // 2 blocks/SM x 152 SMs, wave-perfect
    if (grid > nGroups) grid = nGroups;
    trq_2b_kernel<<<grid, 256>>>(v1b, invar, vec2, (float*)d_out, nGroups);
}

// round 12
// speedup vs baseline: 1.8393x; 1.2262x over previous
#include <cuda_runtime.h>
#include <cstdint>
#include <math.h>

#define NIR 10
#define EPS2 1e-12f
#define INV_SQRT10 0.31622776601683794f

#define TABN 128
#define RMAX 8.0f
#define DELTA (RMAX / (float)TABN)
#define INV_DELTA ((float)TABN / RMAX)

static __device__ __forceinline__ float ex2f(float x){ float r; asm("ex2.approx.f32 %0, %1;" : "=f"(r) : "f"(x)); return r; }
static __device__ __forceinline__ float rcpf(float x){ float r; asm("rcp.approx.f32 %0, %1;" : "=f"(r) : "f"(x)); return r; }
static __device__ __forceinline__ float rsqf(float x){ float r; asm("rsqrt.approx.f32 %0, %1;" : "=f"(r) : "f"(x)); return r; }
static __device__ __forceinline__ float sqrtaf(float x){ float r; asm("sqrt.approx.f32 %0, %1;" : "=f"(r) : "f"(x)); return r; }

static __device__ __forceinline__ float tanh_fast(float z){
    float e = ex2f(z * 2.8853900817779268f);
    float r = rcpf(e + 1.0f);
    return fmaf(-2.0f, r, 1.0f);
}

static __device__ __forceinline__ uint64_t pack2(float lo, float hi){
    uint64_t r; asm("mov.b64 %0, {%1, %2};" : "=l"(r) : "f"(lo), "f"(hi)); return r;
}
static __device__ __forceinline__ float2 unpack2(uint64_t v){
    float2 f; asm("mov.b64 {%0, %1}, %2;" : "=f"(f.x), "=f"(f.y) : "l"(v)); return f;
}
static __device__ __forceinline__ uint64_t fma2(uint64_t a, uint64_t b, uint64_t c){
    uint64_t d; asm("fma.rn.f32x2 %0, %1, %2, %3;" : "=l"(d) : "l"(a), "l"(b), "l"(c)); return d;
}
static __device__ __forceinline__ uint64_t add2(uint64_t a, uint64_t b){
    uint64_t d; asm("add.rn.f32x2 %0, %1, %2;" : "=l"(d) : "l"(a), "l"(b)); return d;
}
static __device__ __forceinline__ uint64_t lo64(float4 w){ return pack2(w.x, w.y); }
static __device__ __forceinline__ uint64_t hi64(float4 w){ return pack2(w.z, w.w); }

// h_v(r) evaluated from shared-staged params:
// sB[0..9]=lw1, [10..19]=nb1, [20..119]=lw2, [120..129]=nb2, [130..139]=wf
static __device__ void eval_h_s(float r, const float* sB, float* h)
{
    float n2 = r * r;
    float g[NIR];
    #pragma unroll
    for (int u = 0; u < NIR; u++){
        float a   = sB[u];
        float arg = fmaf(a * a, n2, EPS2);
        float inv = rsqf(arg);
        float nrm = arg * inv;
        g[u] = tanh_fast(nrm + sB[10 + u]) * inv;
    }
    #pragma unroll
    for (int v = 0; v < NIR; v++){
        float c = 0.0f;
        #pragma unroll
        for (int u = 0; u < NIR; u++)
            c = fmaf(g[u] * sB[u], sB[20 + u * NIR + v], c);
        c *= INV_SQRT10;
        float arg = fmaf(c * c, n2, EPS2);
        float inv = rsqf(arg);
        float nrm = arg * inv;
        float scal2 = tanh_fast(nrm + sB[120 + v]) * inv;
        h[v] = c * scal2 * sB[130 + v] * INV_SQRT10;
    }
}

// ---------------- single fused kernel ----------------
__global__ __launch_bounds__(256, 2) void trq_2b_kernel(
    const float* __restrict__ v1b,   // (B,3)
    const float* __restrict__ invar, // (B,P,2)
    const float* __restrict__ vec2,  // (B,P,6)
    const float* __restrict__ W1,    // (2,10)
    const float* __restrict__ b1,    // (10)
    const float* __restrict__ W2,    // (10,10)
    const float* __restrict__ b2,    // (10)
    const float* __restrict__ lw1,   // (10)
    const float* __restrict__ nb1,   // (10)
    const float* __restrict__ lw2,   // (10,10)
    const float* __restrict__ nb2,   // (10)
    const float* __restrict__ wf,    // (10)
    float* __restrict__ out,         // (B,3)
    int nGroups)
{
    // table rows: 7 x float4; j in 0..4 holds (a_{2j}, b_{2j}, a_{2j+1}, b_{2j+1})
    // row stride 112B, gcd(7,8)=1 -> bank spread for random gather
    __shared__ __align__(16) float4 sTab[TABN][7];      // 14336 B
    __shared__ float sH[TABN + 1][NIR];                 // 5160 B endpoint values
    __shared__ __align__(16) float4 sW2T[25];           // transposed pair layout
    __shared__ float sB[140];                           // build params
    __shared__ float sW1x[NIR], sW1y[NIR], sB1[NIR], sB2[NIR];

    const int tid = threadIdx.x;

    // ---- stage all small params into shared ----
    if (tid < 10)        sB[tid]       = lw1[tid];
    else if (tid < 20)   sB[tid]       = nb1[tid - 10];
    else if (tid < 120)  sB[tid]       = lw2[tid - 20];
    else if (tid < 130)  sB[tid]       = nb2[tid - 120];
    else if (tid < 140)  sB[tid]       = wf[tid - 130];
    else if (tid < 240){
        int q = tid - 140, u = q / 10, v = q % 10;
        reinterpret_cast<float*>(sW2T)[(v >> 1) * 20 + (u >> 1) * 4 + ((u & 1) << 1) + (v & 1)] = W2[q];
    } else if (tid < 250){
        int u = tid - 240;
        sW1x[u] = W1[u];
        sW1y[u] = W1[10 + u];
        sB1[u]  = b1[u];
        sB2[u]  = b2[u];
    }
    __syncthreads();

    // ---- build endpoint values: one eval per thread ----
    if (tid <= TABN){
        float h[NIR];
        eval_h_s((float)tid * DELTA, sB, h);
        #pragma unroll
        for (int v = 0; v < NIR; v++) sH[tid][v] = h[v];
    }
    __syncthreads();

    // ---- derive (a,b) coefficients per interval ----
    if (tid < TABN){
        const float r0 = (float)tid * DELTA;
        #pragma unroll
        for (int j = 0; j < 5; j++){
            float h00 = sH[tid][2*j],     h10 = sH[tid+1][2*j];
            float h01 = sH[tid][2*j + 1], h11 = sH[tid+1][2*j + 1];
            float bb0 = (h10 - h00) * INV_DELTA;
            float bb1 = (h11 - h01) * INV_DELTA;
            float aa0 = fmaf(-bb0, r0, h00);
            float aa1 = fmaf(-bb1, r0, h01);
            sTab[tid][j] = make_float4(aa0, bb0, aa1, bb1);
        }
        sTab[tid][5] = make_float4(0.f, 0.f, 0.f, 0.f);
        sTab[tid][6] = make_float4(0.f, 0.f, 0.f, 0.f);
    }
    __syncthreads();

    const int w    = tid >> 5;
    const int lane = tid & 31;

    // hoist b2 pairs (10 regs)
    uint64_t b2d[5];
    #pragma unroll
    for (int j = 0; j < 5; j++) b2d[j] = pack2(sB2[2*j], sB2[2*j+1]);

    for (int g = blockIdx.x; g < nGroups; g += gridDim.x){
        const int b = g * 8 + w;

        const size_t e0 = (size_t)b * 256 + lane;
        const float2* ivp = reinterpret_cast<const float2*>(invar) + e0;
        const float*  vb  = vec2 + e0 * 6;

        // ---- front-batch all global loads (single DRAM exposure) ----
        float2 iv[8];
        float  vx[8];
        float2 vyz[8];
        #pragma unroll
        for (int i = 0; i < 8; i++){
            iv[i]  = ivp[i * 32];
            const float* vp = vb + i * 192;           // 32*6
            vx[i]  = vp[3];
            vyz[i] = *reinterpret_cast<const float2*>(vp + 4);
        }

        float tx = 0.f, ty = 0.f, tz = 0.f;

        // process elements two at a time: one set of W2 loads feeds BOTH chains
        #pragma unroll
        for (int c = 0; c < 4; c++){
            const int iA = 2 * c, iB = 2 * c + 1;

            // gather indices first (LDS latency overlaps MLP)
            const float n2A = fmaf(vx[iA], vx[iA], fmaf(vyz[iA].x, vyz[iA].x, vyz[iA].y * vyz[iA].y));
            const float n2B = fmaf(vx[iB], vx[iB], fmaf(vyz[iB].x, vyz[iB].x, vyz[iB].y * vyz[iB].y));
            const float rA = sqrtaf(n2A);
            const float rB = sqrtaf(n2B);
            int kA = (int)(rA * INV_DELTA); kA = (kA > TABN - 1) ? (TABN - 1) : kA;
            int kB = (int)(rB * INV_DELTA); kB = (kB > TABN - 1) ? (TABN - 1) : kB;
            const float4* rowA = sTab[kA];
            const float4* rowB = sTab[kB];

            // y1 for both elements
            uint64_t y1A[NIR], y1B[NIR];
            #pragma unroll
            for (int u = 0; u < NIR; u++){
                const float w1xu = sW1x[u];
                const float w1yu = sW1y[u];
                const float b1u  = sB1[u];
                float yA = fmaxf(fmaf(iv[iA].x, w1xu, fmaf(iv[iA].y, w1yu, b1u)), 0.0f);
                float yB = fmaxf(fmaf(iv[iB].x, w1xu, fmaf(iv[iB].y, w1yu, b1u)), 0.0f);
                y1A[u] = pack2(yA, yA);
                y1B[u] = pack2(yB, yB);
            }

            // fused y2 + table-dot, both elements share each W2 quad load
            float SaA = 0.f, SbA = 0.f, SaB = 0.f, SbB = 0.f;
            #pragma unroll
            for (int j = 0; j < 5; j++){
                uint64_t aA = b2d[j], bA = 0ull;
                uint64_t aB = b2d[j], bB = 0ull;
                #pragma unroll
                for (int uu = 0; uu < 5; uu++){
                    float4 wq = sW2T[j * 5 + uu];        // ONE broadcast LDS.128 for two elements
                    uint64_t lo = lo64(wq), hi = hi64(wq);
                    aA = fma2(y1A[2*uu],   lo, aA);
                    aB = fma2(y1B[2*uu],   lo, aB);
                    bA = fma2(y1A[2*uu+1], hi, bA);
                    bB = fma2(y1B[2*uu+1], hi, bB);
                }
                float2 yA2 = unpack2(add2(aA, bA));
                float2 yB2 = unpack2(add2(aB, bB));
                const float m0A = fmaxf(yA2.x, 0.f), m1A = fmaxf(yA2.y, 0.f);
                const float m0B = fmaxf(yB2.x, 0.f), m1B = fmaxf(yB2.y, 0.f);
                const float4 tA = rowA[j];
                const float4 tB = rowB[j];
                SaA = fmaf(m0A, tA.x, SaA); SbA = fmaf(m0A, tA.y, SbA);
                SaA = fmaf(m1A, tA.z, SaA); SbA = fmaf(m1A, tA.w, SbA);
                SaB = fmaf(m0B, tB.x, SaB); SbB = fmaf(m0B, tB.y, SbB);
                SaB = fmaf(m1B, tB.z, SaB); SbB = fmaf(m1B, tB.w, SbB);
            }
            const float SA = fmaf(rA, SbA, SaA);
            const float SB = fmaf(rB, SbB, SaB);

            tx = fmaf(vx[iA],    SA, tx);  tx = fmaf(vx[iB],    SB, tx);
            ty = fmaf(vyz[iA].x, SA, ty);  ty = fmaf(vyz[iB].x, SB, ty);
            tz = fmaf(vyz[iA].y, SA, tz);  tz = fmaf(vyz[iB].y, SB, tz);
        }

        // warp reduction (warp owns batch b entirely)
        #pragma unroll
        for (int off = 16; off > 0; off >>= 1){
            tx += __shfl_down_sync(0xFFFFFFFFu, tx, off);
            ty += __shfl_down_sync(0xFFFFFFFFu, ty, off);
            tz += __shfl_down_sync(0xFFFFFFFFu, tz, off);
        }
        if (lane == 0){
            const float a0 = v1b[b*3+0], a1 = v1b[b*3+1], a2 = v1b[b*3+2];
            out[b*3+0] = a1 * tz - a2 * ty;
            out[b*3+1] = a2 * tx - a0 * tz;
            out[b*3+2] = a0 * ty - a1 * tx;
        }
    }
}

extern "C" void kernel_launch(void* const* d_in, const int* in_sizes, int n_in,
                              void* d_out, int out_size)
{
    const float* v1b   = (const float*)d_in[0];
    const float* invar = (const float*)d_in[1];
    const float* vec2  = (const float*)d_in[2];
    const float* W1    = (const float*)d_in[3];
    const float* b1    = (const float*)d_in[4];
    const float* W2    = (const float*)d_in[5];
    const float* b2    = (const float*)d_in[6];
    const float* lw1   = (const float*)d_in[7];
    const float* nb1   = (const float*)d_in[8];
    const float* lw2   = (const float*)d_in[9];
    const float* nb2   = (const float*)d_in[10];
    const float* wf    = (const float*)d_in[11];

    const int B = out_size / 3;        // 4096
    const int nGroups = B / 8;         // 512

    int grid = 304;                    // 2 blocks/SM x 152 SMs, wave-perfect
    if (grid > nGroups) grid = nGroups;
    trq_2b_kernel<<<grid, 256>>>(v1b, invar, vec2, W1, b1, W2, b2,
                                 lw1, nb1, lw2, nb2, wf,
                                 (float*)d_out, nGroups);
}

// round 13
// speedup vs baseline: 1.8636x; 1.0133x over previous
#include <cuda_runtime.h>
#include <cstdint>
#include <math.h>

#define NIR 10
#define EPS2 1e-12f
#define INV_SQRT10 0.31622776601683794f

#define TABN 128
#define RMAX 8.0f
#define DELTA (RMAX / (float)TABN)
#define INV_DELTA ((float)TABN / RMAX)

static __device__ __forceinline__ float ex2f(float x){ float r; asm("ex2.approx.f32 %0, %1;" : "=f"(r) : "f"(x)); return r; }
static __device__ __forceinline__ float rcpf(float x){ float r; asm("rcp.approx.f32 %0, %1;" : "=f"(r) : "f"(x)); return r; }
static __device__ __forceinline__ float rsqf(float x){ float r; asm("rsqrt.approx.f32 %0, %1;" : "=f"(r) : "f"(x)); return r; }
static __device__ __forceinline__ float sqrtaf(float x){ float r; asm("sqrt.approx.f32 %0, %1;" : "=f"(r) : "f"(x)); return r; }

static __device__ __forceinline__ float tanh_fast(float z){
    float e = ex2f(z * 2.8853900817779268f);
    float r = rcpf(e + 1.0f);
    return fmaf(-2.0f, r, 1.0f);
}

static __device__ __forceinline__ uint64_t pack2(float lo, float hi){
    uint64_t r; asm("mov.b64 %0, {%1, %2};" : "=l"(r) : "f"(lo), "f"(hi)); return r;
}
static __device__ __forceinline__ float2 unpack2(uint64_t v){
    float2 f; asm("mov.b64 {%0, %1}, %2;" : "=f"(f.x), "=f"(f.y) : "l"(v)); return f;
}
static __device__ __forceinline__ uint64_t fma2(uint64_t a, uint64_t b, uint64_t c){
    uint64_t d; asm("fma.rn.f32x2 %0, %1, %2, %3;" : "=l"(d) : "l"(a), "l"(b), "l"(c)); return d;
}
static __device__ __forceinline__ uint64_t add2(uint64_t a, uint64_t b){
    uint64_t d; asm("add.rn.f32x2 %0, %1, %2;" : "=l"(d) : "l"(a), "l"(b)); return d;
}
static __device__ __forceinline__ uint64_t lo64(float4 w){ return pack2(w.x, w.y); }
static __device__ __forceinline__ uint64_t hi64(float4 w){ return pack2(w.z, w.w); }

// h_v(r) evaluated from shared-staged params:
// sB[0..9]=lw1, [10..19]=nb1, [20..119]=lw2, [120..129]=nb2, [130..139]=wf
static __device__ void eval_h_s(float r, const float* sB, float* h)
{
    float n2 = r * r;
    float g[NIR];
    #pragma unroll
    for (int u = 0; u < NIR; u++){
        float a   = sB[u];
        float arg = fmaf(a * a, n2, EPS2);
        float inv = rsqf(arg);
        float nrm = arg * inv;
        g[u] = tanh_fast(nrm + sB[10 + u]) * inv;
    }
    #pragma unroll
    for (int v = 0; v < NIR; v++){
        float c = 0.0f;
        #pragma unroll
        for (int u = 0; u < NIR; u++)
            c = fmaf(g[u] * sB[u], sB[20 + u * NIR + v], c);
        c *= INV_SQRT10;
        float arg = fmaf(c * c, n2, EPS2);
        float inv = rsqf(arg);
        float nrm = arg * inv;
        float scal2 = tanh_fast(nrm + sB[120 + v]) * inv;
        h[v] = c * scal2 * sB[130 + v] * INV_SQRT10;
    }
}

// ---------------- single fused kernel ----------------
__global__ __launch_bounds__(256, 2) void trq_2b_kernel(
    const float* __restrict__ v1b,   // (B,3)
    const float* __restrict__ invar, // (B,P,2)
    const float* __restrict__ vec2,  // (B,P,6)
    const float* __restrict__ W1,    // (2,10)
    const float* __restrict__ b1,    // (10)
    const float* __restrict__ W2,    // (10,10)
    const float* __restrict__ b2,    // (10)
    const float* __restrict__ lw1,   // (10)
    const float* __restrict__ nb1,   // (10)
    const float* __restrict__ lw2,   // (10,10)
    const float* __restrict__ nb2,   // (10)
    const float* __restrict__ wf,    // (10)
    float* __restrict__ out,         // (B,3)
    int nGroups)
{
    // table rows: 7 x float4; j in 0..4 holds (a_{2j}, a_{2j+1}, b_{2j}, b_{2j+1})
    // row stride 112B, gcd(7,8)=1 -> bank spread for random gather
    __shared__ __align__(16) float4 sTab[TABN][7];      // 14336 B
    __shared__ float sH[TABN + 1][NIR];                 // 5160 B endpoint values
    __shared__ __align__(16) float4 sW2T[25];           // transposed pair layout
    __shared__ __align__(16) float4 sW1q[NIR];          // (w1x, w1y, b1, 0) per u
    __shared__ float sB[140];                           // build params
    __shared__ float sB2[NIR];

    const int tid = threadIdx.x;

    // ---- stage all small params into shared ----
    if (tid < 10)        sB[tid]       = lw1[tid];
    else if (tid < 20)   sB[tid]       = nb1[tid - 10];
    else if (tid < 120)  sB[tid]       = lw2[tid - 20];
    else if (tid < 130)  sB[tid]       = nb2[tid - 120];
    else if (tid < 140)  sB[tid]       = wf[tid - 130];
    else if (tid < 240){
        int q = tid - 140, u = q / 10, v = q % 10;
        reinterpret_cast<float*>(sW2T)[(v >> 1) * 20 + (u >> 1) * 4 + ((u & 1) << 1) + (v & 1)] = W2[q];
    } else if (tid < 250){
        int u = tid - 240;
        sW1q[u] = make_float4(W1[u], W1[10 + u], b1[u], 0.0f);
        sB2[u]  = b2[u];
    }
    __syncthreads();

    // ---- build endpoint values: one eval per thread ----
    if (tid <= TABN){
        float h[NIR];
        eval_h_s((float)tid * DELTA, sB, h);
        #pragma unroll
        for (int v = 0; v < NIR; v++) sH[tid][v] = h[v];
    }
    __syncthreads();

    // ---- derive (a0,a1,b0,b1) coefficients per interval ----
    if (tid < TABN){
        const float r0 = (float)tid * DELTA;
        #pragma unroll
        for (int j = 0; j < 5; j++){
            float h00 = sH[tid][2*j],     h10 = sH[tid+1][2*j];
            float h01 = sH[tid][2*j + 1], h11 = sH[tid+1][2*j + 1];
            float bb0 = (h10 - h00) * INV_DELTA;
            float bb1 = (h11 - h01) * INV_DELTA;
            float aa0 = fmaf(-bb0, r0, h00);
            float aa1 = fmaf(-bb1, r0, h01);
            sTab[tid][j] = make_float4(aa0, aa1, bb0, bb1);
        }
        sTab[tid][5] = make_float4(0.f, 0.f, 0.f, 0.f);
        sTab[tid][6] = make_float4(0.f, 0.f, 0.f, 0.f);
    }
    __syncthreads();

    const int w    = tid >> 5;
    const int lane = tid & 31;

    // hoist b2 pairs (10 regs)
    uint64_t b2d[5];
    #pragma unroll
    for (int j = 0; j < 5; j++) b2d[j] = pack2(sB2[2*j], sB2[2*j+1]);

    for (int g = blockIdx.x; g < nGroups; g += gridDim.x){
        const int b = g * 8 + w;

        const size_t e0 = (size_t)b * 256 + lane;
        const float2* ivp = reinterpret_cast<const float2*>(invar) + e0;
        const float*  vb  = vec2 + e0 * 6;

        // ---- front-batch all global loads (single DRAM exposure) ----
        float2 iv[8];
        float  vx[8];
        float2 vyz[8];
        #pragma unroll
        for (int i = 0; i < 8; i++){
            iv[i]  = ivp[i * 32];
            const float* vp = vb + i * 192;           // 32*6
            vx[i]  = vp[3];
            vyz[i] = *reinterpret_cast<const float2*>(vp + 4);
        }

        float tx = 0.f, ty = 0.f, tz = 0.f;

        // process elements two at a time: shared W1/W2 loads feed BOTH chains
        #pragma unroll
        for (int c = 0; c < 4; c++){
            const int iA = 2 * c, iB = 2 * c + 1;

            // gather indices first (LDS latency overlaps MLP)
            const float n2A = fmaf(vx[iA], vx[iA], fmaf(vyz[iA].x, vyz[iA].x, vyz[iA].y * vyz[iA].y));
            const float n2B = fmaf(vx[iB], vx[iB], fmaf(vyz[iB].x, vyz[iB].x, vyz[iB].y * vyz[iB].y));
            const float rA = sqrtaf(n2A);
            const float rB = sqrtaf(n2B);
            int kA = (int)(rA * INV_DELTA); kA = (kA > TABN - 1) ? (TABN - 1) : kA;
            int kB = (int)(rB * INV_DELTA); kB = (kB > TABN - 1) ? (TABN - 1) : kB;
            const float4* rowA = sTab[kA];
            const float4* rowB = sTab[kB];

            // y1 for both elements: one LDS.128 per u feeds both
            uint64_t y1A[NIR], y1B[NIR];
            #pragma unroll
            for (int u = 0; u < NIR; u++){
                const float4 wq = sW1q[u];   // (w1x, w1y, b1, 0)
                float yA = fmaxf(fmaf(iv[iA].x, wq.x, fmaf(iv[iA].y, wq.y, wq.z)), 0.0f);
                float yB = fmaxf(fmaf(iv[iB].x, wq.x, fmaf(iv[iB].y, wq.y, wq.z)), 0.0f);
                y1A[u] = pack2(yA, yA);
                y1B[u] = pack2(yB, yB);
            }

            // fused y2 + f32x2 table-dot, both elements share each W2 quad load
            uint64_t dAa = 0ull, dAb = 0ull, dBa = 0ull, dBb = 0ull;
            #pragma unroll
            for (int j = 0; j < 5; j++){
                uint64_t aA = b2d[j], bA = 0ull;
                uint64_t aB = b2d[j], bB = 0ull;
                #pragma unroll
                for (int uu = 0; uu < 5; uu++){
                    float4 wq = sW2T[j * 5 + uu];        // ONE broadcast LDS.128 for two elements
                    uint64_t lo = lo64(wq), hi = hi64(wq);
                    aA = fma2(y1A[2*uu],   lo, aA);
                    aB = fma2(y1B[2*uu],   lo, aB);
                    bA = fma2(y1A[2*uu+1], hi, bA);
                    bB = fma2(y1B[2*uu+1], hi, bB);
                }
                float2 yA2 = unpack2(add2(aA, bA));
                float2 yB2 = unpack2(add2(aB, bB));
                const uint64_t pmA = pack2(fmaxf(yA2.x, 0.f), fmaxf(yA2.y, 0.f));
                const uint64_t pmB = pack2(fmaxf(yB2.x, 0.f), fmaxf(yB2.y, 0.f));
                const float4 tA = rowA[j];   // (a0,a1,b0,b1)
                const float4 tB = rowB[j];
                dAa = fma2(pmA, lo64(tA), dAa);
                dAb = fma2(pmA, hi64(tA), dAb);
                dBa = fma2(pmB, lo64(tB), dBa);
                dBb = fma2(pmB, hi64(tB), dBb);
            }
            const float2 fAa = unpack2(dAa), fAb = unpack2(dAb);
            const float2 fBa = unpack2(dBa), fBb = unpack2(dBb);
            const float SA = fmaf(rA, fAb.x + fAb.y, fAa.x + fAa.y);
            const float SB = fmaf(rB, fBb.x + fBb.y, fBa.x + fBa.y);

            tx = fmaf(vx[iA],    SA, tx);  tx = fmaf(vx[iB],    SB, tx);
            ty = fmaf(vyz[iA].x, SA, ty);  ty = fmaf(vyz[iB].x, SB, ty);
            tz = fmaf(vyz[iA].y, SA, tz);  tz = fmaf(vyz[iB].y, SB, tz);
        }

        // warp reduction (warp owns batch b entirely)
        #pragma unroll
        for (int off = 16; off > 0; off >>= 1){
            tx += __shfl_down_sync(0xFFFFFFFFu, tx, off);
            ty += __shfl_down_sync(0xFFFFFFFFu, ty, off);
            tz += __shfl_down_sync(0xFFFFFFFFu, tz, off);
        }
        if (lane == 0){
            const float a0 = v1b[b*3+0], a1 = v1b[b*3+1], a2 = v1b[b*3+2];
            out[b*3+0] = a1 * tz - a2 * ty;
            out[b*3+1] = a2 * tx - a0 * tz;
            out[b*3+2] = a0 * ty - a1 * tx;
        }
    }
}

extern "C" void kernel_launch(void* const* d_in, const int* in_sizes, int n_in,
                              void* d_out, int out_size)
{
    const float* v1b   = (const float*)d_in[0];
    const float* invar = (const float*)d_in[1];
    const float* vec2  = (const float*)d_in[2];
    const float* W1    = (const float*)d_in[3];
    const float* b1    = (const float*)d_in[4];
    const float* W2    = (const float*)d_in[5];
    const float* b2    = (const float*)d_in[6];
    const float* lw1   = (const float*)d_in[7];
    const float* nb1   = (const float*)d_in[8];
    const float* lw2   = (const float*)d_in[9];
    const float* nb2   = (const float*)d_in[10];
    const float* wf    = (const float*)d_in[11];

    const int B = out_size / 3;        // 4096
    const int nGroups = B / 8;         // 512

    int grid = 304;                    // 2 blocks/SM x 152 SMs
    if (grid > nGroups) grid = nGroups;
    trq_2b_kernel<<<grid, 256>>>(v1b, invar, vec2, W1, b1, W2, b2,
                                 lw1, nb1, lw2, nb2, wf,
                                 (float*)d_out, nGroups);
}